// round 1
// baseline (speedup 1.0000x reference)
#include <cuda_runtime.h>
#include <math.h>

// ---------------------------------------------------------------------------
// SparseConvNet: 6 partial-conv layers, each = masked conv / mask-sum conv
// + bias + batchnorm(stats over N,H,W) + relu(first 5) + mask maxpool.
// N=4, H=W=1024. Layers: (1,16,11)(16,16,7)(16,16,5)(16,16,3)(16,16,3)(16,1,1)
// ---------------------------------------------------------------------------

#define HW   (1024 * 1024)
#define IMW  1024
#define NPIX (4LL * HW)   // elements per channel for BN stats

// Scratch (device globals: allocation-free per harness rules)
__device__ float  g_h0[4 * 16 * HW];   // 256 MB ping
__device__ float  g_h1[4 * 16 * HW];   // 256 MB pong
__device__ float  g_m0[4 * HW];        // 16 MB mask ping
__device__ float  g_m1[4 * HW];        // 16 MB mask pong
__device__ double g_stats[6 * 32];     // per layer: [co] sum, [16+co] sumsq
__device__ float2 g_affine[6 * 16];    // per layer per channel: (a, b)

__global__ void zero_stats_k() {
    if (threadIdx.x < 6 * 32) g_stats[threadIdx.x] = 0.0;
}

// stats -> affine: a = gamma * rsqrt(var+1e-5), b = beta - mean * a
__global__ void affine_k(const double* __restrict__ st,
                         const float* __restrict__ gam,
                         const float* __restrict__ bet,
                         float2* __restrict__ ab, int nch) {
    int c = threadIdx.x;
    if (c >= nch) return;
    double mean = st[c] / (double)NPIX;
    double var  = st[16 + c] / (double)NPIX - mean * mean;
    float inv = rsqrtf((float)var + 1e-5f);
    float a = gam[c] * inv;
    ab[c] = make_float2(a, bet[c] - (float)mean * a);
}

// ---------------------------------------------------------------------------
// Main fused conv kernel.
//   - loads mask tile + input tile (applying prev-layer BN affine + relu +
//     mask multiply inline)
//   - direct conv to 16 output channels, 4 pixels per thread
//   - mask-sum conv + maxpool from the same smem mask tile
//   - writes pre-BN y and pooled mask, accumulates per-channel sum/sumsq
// ---------------------------------------------------------------------------
template <int K, int CIN, bool AFF>
__global__ void __launch_bounds__(128) conv_k(
    const float* __restrict__ in, long long inNS,
    const float* __restrict__ mk, long long mkNS,
    const float* __restrict__ wG, const float* __restrict__ bias,
    const float2* __restrict__ aff,
    float* __restrict__ outH, float* __restrict__ outM,
    double* __restrict__ stats) {
    constexpr int TX = 32, TY = 16, P = K / 2;
    constexpr int IW = TX + K - 1, IH = TY + K - 1;
    constexpr int SXN = CIN * IH * IW;
    constexpr int SMN = IH * IW;
    constexpr int SWOFF = ((SXN + SMN + 3) / 4) * 4;
    constexpr int SWN = CIN * K * K * 16;

    extern __shared__ float sm[];
    float* sX  = sm;                 // [CIN][IH][IW] masked+activated input
    float* sMk = sm + SXN;           // [IH][IW] mask tile
    float* sW  = sm + SWOFF;         // [CIN][K][K][16co]
    float* sR  = sm + SWOFF + SWN;   // 128 floats reduce buf

    const int tid = threadIdx.x;
    const int n = blockIdx.z;
    const int x0 = blockIdx.x * TX - P;
    const int y0 = blockIdx.y * TY - P;

    // weights: wG[co][ci][dy][dx] -> sW[((ci*K+dy)*K+dx)*16 + co]
    for (int i = tid; i < SWN; i += 128) {
        int co = i & 15;
        int rest = i >> 4;  // (ci*K+dy)*K+dx
        sW[i] = wG[co * (CIN * K * K) + rest];
    }
    // mask tile (zero pad OOB)
    const float* mkn = mk + (long long)n * mkNS;
    for (int i = tid; i < SMN; i += 128) {
        int ly = i / IW, lx = i - ly * IW;
        int gy = y0 + ly, gx = x0 + lx;
        float m = 0.f;
        if (gy >= 0 && gy < 1024 && gx >= 0 && gx < 1024) m = mkn[gy * IMW + gx];
        sMk[i] = m;
    }
    __syncthreads();

    // input tile: xm = relu(a*h+b) * mask  (first layer: raw * mask)
    const float* inn = in + (long long)n * inNS;
    for (int ci = 0; ci < CIN; ci++) {
        float2 ab = make_float2(1.f, 0.f);
        if (AFF) ab = aff[ci];
        for (int i = tid; i < SMN; i += 128) {
            int ly = i / IW, lx = i - ly * IW;
            int gy = y0 + ly, gx = x0 + lx;
            float v = 0.f;
            if (gy >= 0 && gy < 1024 && gx >= 0 && gx < 1024) {
                v = inn[(long long)ci * HW + gy * IMW + gx];
                if (AFF) v = fmaxf(fmaf(v, ab.x, ab.y), 0.f);
                v *= sMk[i];
            }
            sX[ci * SMN + i] = v;
        }
    }
    __syncthreads();

    const int tx = tid & 31;   // x within tile
    const int tq = tid >> 5;   // y quad (4 rows each)

    float acc[64];             // acc[co*4 + py]
#pragma unroll
    for (int i = 0; i < 64; i++) acc[i] = 0.f;

    for (int ci = 0; ci < CIN; ci++) {
        const float* xb = sX + ci * SMN + (tq * 4) * IW + tx;
        const float* wb = sW + ci * (K * K * 16);
#pragma unroll 1
        for (int dy = 0; dy < K; dy++) {
            const float* xr = xb + dy * IW;
            const float* wr = wb + dy * (K * 16);
#pragma unroll
            for (int dx = 0; dx < K; dx++) {
                float v0 = xr[dx];
                float v1 = xr[dx + IW];
                float v2 = xr[dx + 2 * IW];
                float v3 = xr[dx + 3 * IW];
                const float4* wv = (const float4*)(wr + dx * 16);
#pragma unroll
                for (int j = 0; j < 4; j++) {
                    float4 w = wv[j];
                    acc[(4 * j + 0) * 4 + 0] = fmaf(v0, w.x, acc[(4 * j + 0) * 4 + 0]);
                    acc[(4 * j + 0) * 4 + 1] = fmaf(v1, w.x, acc[(4 * j + 0) * 4 + 1]);
                    acc[(4 * j + 0) * 4 + 2] = fmaf(v2, w.x, acc[(4 * j + 0) * 4 + 2]);
                    acc[(4 * j + 0) * 4 + 3] = fmaf(v3, w.x, acc[(4 * j + 0) * 4 + 3]);
                    acc[(4 * j + 1) * 4 + 0] = fmaf(v0, w.y, acc[(4 * j + 1) * 4 + 0]);
                    acc[(4 * j + 1) * 4 + 1] = fmaf(v1, w.y, acc[(4 * j + 1) * 4 + 1]);
                    acc[(4 * j + 1) * 4 + 2] = fmaf(v2, w.y, acc[(4 * j + 1) * 4 + 2]);
                    acc[(4 * j + 1) * 4 + 3] = fmaf(v3, w.y, acc[(4 * j + 1) * 4 + 3]);
                    acc[(4 * j + 2) * 4 + 0] = fmaf(v0, w.z, acc[(4 * j + 2) * 4 + 0]);
                    acc[(4 * j + 2) * 4 + 1] = fmaf(v1, w.z, acc[(4 * j + 2) * 4 + 1]);
                    acc[(4 * j + 2) * 4 + 2] = fmaf(v2, w.z, acc[(4 * j + 2) * 4 + 2]);
                    acc[(4 * j + 2) * 4 + 3] = fmaf(v3, w.z, acc[(4 * j + 2) * 4 + 3]);
                    acc[(4 * j + 3) * 4 + 0] = fmaf(v0, w.w, acc[(4 * j + 3) * 4 + 0]);
                    acc[(4 * j + 3) * 4 + 1] = fmaf(v1, w.w, acc[(4 * j + 3) * 4 + 1]);
                    acc[(4 * j + 3) * 4 + 2] = fmaf(v2, w.w, acc[(4 * j + 3) * 4 + 2]);
                    acc[(4 * j + 3) * 4 + 3] = fmaf(v3, w.w, acc[(4 * j + 3) * 4 + 3]);
                }
            }
        }
    }

    // mask-sum conv + mask maxpool (mask >= 0, so 0-init max == -inf init)
    float s[4] = {0.f, 0.f, 0.f, 0.f};
    float mm[4] = {0.f, 0.f, 0.f, 0.f};
    {
        const float* mb = sMk + (tq * 4) * IW + tx;
#pragma unroll 1
        for (int dy = 0; dy < K; dy++) {
#pragma unroll
            for (int dx = 0; dx < K; dx++) {
#pragma unroll
                for (int py = 0; py < 4; py++) {
                    float m = mb[(dy + py) * IW + dx];
                    s[py] += m;
                    mm[py] = fmaxf(mm[py], m);
                }
            }
        }
    }
    float inv[4];
#pragma unroll
    for (int py = 0; py < 4; py++) inv[py] = 1.0f / (s[py] + 1e-8f);

    const int gy = blockIdx.y * TY + tq * 4;
    const int gx = blockIdx.x * TX + tx;

    float* mo = outM + (long long)n * HW + gy * IMW + gx;
#pragma unroll
    for (int py = 0; py < 4; py++) mo[py * IMW] = mm[py];

    float* ho = outH + ((long long)n * 16) * HW + gy * IMW + gx;
    const int lane = tid & 31;
    const int warp = tid >> 5;
#pragma unroll
    for (int co = 0; co < 16; co++) {
        float bc = bias[co];
        float p1 = 0.f, p2 = 0.f;
#pragma unroll
        for (int py = 0; py < 4; py++) {
            float y = fmaf(acc[co * 4 + py], inv[py], bc);
            ho[(long long)co * HW + py * IMW] = y;
            p1 += y;
            p2 = fmaf(y, y, p2);
        }
#pragma unroll
        for (int o = 16; o; o >>= 1) {
            p1 += __shfl_xor_sync(0xffffffffu, p1, o);
            p2 += __shfl_xor_sync(0xffffffffu, p2, o);
        }
        if (lane == 0) {
            sR[(co * 2 + 0) * 4 + warp] = p1;
            sR[(co * 2 + 1) * 4 + warp] = p2;
        }
    }
    __syncthreads();
    if (tid < 32) {
        float v = sR[tid * 4 + 0] + sR[tid * 4 + 1] + sR[tid * 4 + 2] + sR[tid * 4 + 3];
        int co = tid >> 1, which = tid & 1;
        atomicAdd(&stats[which * 16 + co], (double)v);
    }
}

// ---------------------------------------------------------------------------
// Layer 6: 1x1 partial conv, 16 -> 1 channel. s = mask, so
//   y = (sum_c w_c * relu(a_c h_c + b_c)) * mask / (mask + 1e-8) + bias
// ---------------------------------------------------------------------------
__global__ void conv1x1_k(const float* __restrict__ h,
                          const float* __restrict__ mk,
                          const float* __restrict__ w6,
                          const float* __restrict__ b6,
                          const float2* __restrict__ aff,
                          float* __restrict__ y,
                          double* __restrict__ stats) {
    __shared__ float swv[16];
    __shared__ float2 sab[16];
    __shared__ float r1[8], r2[8];
    if (threadIdx.x < 16) {
        swv[threadIdx.x] = w6[threadIdx.x];
        sab[threadIdx.x] = aff[threadIdx.x];
    }
    __syncthreads();
    float bb = b6[0];
    float p1 = 0.f, p2 = 0.f;
    for (long long i = (long long)blockIdx.x * blockDim.x + threadIdx.x;
         i < 4LL * HW; i += (long long)gridDim.x * blockDim.x) {
        long long n = i >> 20;        // / HW
        long long p = i & (HW - 1);   // % HW
        float m = mk[i];
        float accv = 0.f;
#pragma unroll
        for (int c = 0; c < 16; c++) {
            float v = h[(n * 16 + c) * HW + p];
            float2 ab = sab[c];
            v = fmaxf(fmaf(v, ab.x, ab.y), 0.f);
            accv = fmaf(swv[c], v, accv);
        }
        float r = 1.0f / (m + 1e-8f);
        float yv = fmaf(accv * m, r, bb);
        y[i] = yv;
        p1 += yv;
        p2 = fmaf(yv, yv, p2);
    }
#pragma unroll
    for (int o = 16; o; o >>= 1) {
        p1 += __shfl_xor_sync(0xffffffffu, p1, o);
        p2 += __shfl_xor_sync(0xffffffffu, p2, o);
    }
    int warp = threadIdx.x >> 5, lane = threadIdx.x & 31;
    if (lane == 0) { r1[warp] = p1; r2[warp] = p2; }
    __syncthreads();
    if (threadIdx.x == 0) {
        float a = 0.f, b = 0.f;
        for (int w = 0; w < (int)(blockDim.x >> 5); w++) { a += r1[w]; b += r2[w]; }
        atomicAdd(&stats[0], (double)a);
        atomicAdd(&stats[16], (double)b);
    }
}

// Final BN (no relu): out = a * y + b
__global__ void final_k(const float* __restrict__ y,
                        const float2* __restrict__ ab,
                        float* __restrict__ o) {
    float2 t = ab[0];
    for (long long i = (long long)blockIdx.x * blockDim.x + threadIdx.x;
         i < 4LL * HW; i += (long long)gridDim.x * blockDim.x)
        o[i] = fmaf(y[i], t.x, t.y);
}

// ---------------------------------------------------------------------------
static constexpr int smem_bytes(int K, int CIN) {
    int IW = 32 + K - 1, IH = 16 + K - 1;
    int sx = CIN * IH * IW, smk = IH * IW;
    int swoff = ((sx + smk + 3) / 4) * 4;
    return (swoff + CIN * K * K * 16 + 128) * 4;
}

extern "C" void kernel_launch(void* const* d_in, const int* in_sizes, int n_in,
                              void* d_out, int out_size) {
    (void)in_sizes; (void)n_in; (void)out_size;
    const float* x = (const float*)d_in[0];
    const float *wp[6], *bp[6], *gp[6], *btp[6];
    for (int i = 0; i < 6; i++) {
        wp[i]  = (const float*)d_in[1 + 4 * i];
        bp[i]  = (const float*)d_in[2 + 4 * i];
        gp[i]  = (const float*)d_in[3 + 4 * i];
        btp[i] = (const float*)d_in[4 + 4 * i];
    }

    float *h0, *h1, *m0, *m1;
    double* st;
    float2* ab;
    cudaGetSymbolAddress((void**)&h0, g_h0);
    cudaGetSymbolAddress((void**)&h1, g_h1);
    cudaGetSymbolAddress((void**)&m0, g_m0);
    cudaGetSymbolAddress((void**)&m1, g_m1);
    cudaGetSymbolAddress((void**)&st, g_stats);
    cudaGetSymbolAddress((void**)&ab, g_affine);

    cudaFuncSetAttribute(conv_k<11, 1, false>, cudaFuncAttributeMaxDynamicSharedMemorySize, smem_bytes(11, 1));
    cudaFuncSetAttribute(conv_k<7, 16, true>,  cudaFuncAttributeMaxDynamicSharedMemorySize, smem_bytes(7, 16));
    cudaFuncSetAttribute(conv_k<5, 16, true>,  cudaFuncAttributeMaxDynamicSharedMemorySize, smem_bytes(5, 16));
    cudaFuncSetAttribute(conv_k<3, 16, true>,  cudaFuncAttributeMaxDynamicSharedMemorySize, smem_bytes(3, 16));

    dim3 grid(1024 / 32, 1024 / 16, 4);
    dim3 blk(128);

    zero_stats_k<<<1, 192>>>();

    // L1: data = x[:,0], mask = x[:,1] (N-stride 2*HW)
    conv_k<11, 1, false><<<grid, blk, smem_bytes(11, 1)>>>(
        x, 2LL * HW, x + HW, 2LL * HW, wp[0], bp[0], nullptr, h0, m0, st + 0);
    affine_k<<<1, 16>>>(st + 0, gp[0], btp[0], ab + 0, 16);

    conv_k<7, 16, true><<<grid, blk, smem_bytes(7, 16)>>>(
        h0, 16LL * HW, m0, (long long)HW, wp[1], bp[1], ab + 0, h1, m1, st + 32);
    affine_k<<<1, 16>>>(st + 32, gp[1], btp[1], ab + 16, 16);

    conv_k<5, 16, true><<<grid, blk, smem_bytes(5, 16)>>>(
        h1, 16LL * HW, m1, (long long)HW, wp[2], bp[2], ab + 16, h0, m0, st + 64);
    affine_k<<<1, 16>>>(st + 64, gp[2], btp[2], ab + 32, 16);

    conv_k<3, 16, true><<<grid, blk, smem_bytes(3, 16)>>>(
        h0, 16LL * HW, m0, (long long)HW, wp[3], bp[3], ab + 32, h1, m1, st + 96);
    affine_k<<<1, 16>>>(st + 96, gp[3], btp[3], ab + 48, 16);

    conv_k<3, 16, true><<<grid, blk, smem_bytes(3, 16)>>>(
        h1, 16LL * HW, m1, (long long)HW, wp[4], bp[4], ab + 48, h0, m0, st + 128);
    affine_k<<<1, 16>>>(st + 128, gp[4], btp[4], ab + 64, 16);

    conv1x1_k<<<1184, 256>>>(h0, m0, wp[5], bp[5], ab + 64, h1, st + 160);
    affine_k<<<1, 16>>>(st + 160, gp[5], btp[5], ab + 80, 1);

    final_k<<<4096, 256>>>(h1, ab + 80, (float*)d_out);
}

// round 2
// speedup vs baseline: 1.4336x; 1.4336x over previous
#include <cuda_runtime.h>
#include <math.h>

// ---------------------------------------------------------------------------
// SparseConvNet: 6 partial-conv layers. N=4, H=W=1024.
// Layers: (1,16,11)(16,16,7)(16,16,5)(16,16,3)(16,16,3)(16,1,1)
// Round 2: packed fma.rn.f32x2 (FFMA2) over output-channel pairs,
//          column-major smem input, ci-chunked staging for occupancy.
// ---------------------------------------------------------------------------

#define HW   (1024 * 1024)
#define IMW  1024
#define NPIX (4LL * HW)

__device__ float  g_h0[4 * 16 * HW];
__device__ float  g_h1[4 * 16 * HW];
__device__ float  g_m0[4 * HW];
__device__ float  g_m1[4 * HW];
__device__ double g_stats[6 * 32];
__device__ float2 g_affine[6 * 16];

typedef unsigned long long u64;

__device__ __forceinline__ u64 dup2(float v) {
    u64 r;
    asm("mov.b64 %0, {%1, %1};" : "=l"(r) : "f"(v));
    return r;
}
__device__ __forceinline__ void fma2(u64& d, u64 a, u64 b) {
    asm("fma.rn.f32x2 %0, %1, %2, %0;" : "+l"(d) : "l"(a), "l"(b));
}
__device__ __forceinline__ void unpk(float& lo, float& hi, u64 v) {
    asm("mov.b64 {%0, %1}, %2;" : "=f"(lo), "=f"(hi) : "l"(v));
}

__global__ void zero_stats_k() {
    if (threadIdx.x < 6 * 32) g_stats[threadIdx.x] = 0.0;
}

__global__ void affine_k(const double* __restrict__ st,
                         const float* __restrict__ gam,
                         const float* __restrict__ bet,
                         float2* __restrict__ ab, int nch) {
    int c = threadIdx.x;
    if (c >= nch) return;
    double mean = st[c] / (double)NPIX;
    double var  = st[16 + c] / (double)NPIX - mean * mean;
    float inv = rsqrtf((float)var + 1e-5f);
    float a = gam[c] * inv;
    ab[c] = make_float2(a, bet[c] - (float)mean * a);
}

// ---------------------------------------------------------------------------
// Fused partial-conv layer. Output tile 32x16, 128 threads, 4 px/thread,
// 16 output channels as 8 packed f32x2 channel-pairs.
// ---------------------------------------------------------------------------
template <int K, int CIN, int CH, bool AFF>
__global__ void __launch_bounds__(128, 4) conv_k(
    const float* __restrict__ in, long long inNS,
    const float* __restrict__ mk, long long mkNS,
    const float* __restrict__ wG, const float* __restrict__ bias,
    const float2* __restrict__ aff,
    float* __restrict__ outH, float* __restrict__ outM,
    double* __restrict__ stats) {
    constexpr int TX = 32, TY = 16, P = K / 2;
    constexpr int IW = TX + K - 1;           // input tile width
    constexpr int IH = TY + K - 1;           // input tile height
    constexpr int IHP = IH | 1;              // odd row pitch (col-major)
    constexpr int SMN = IH * IW;             // mask tile (row-major)
    constexpr int SXN = CH * IW * IHP;       // staged input (col-major)
    constexpr int SWOFF = ((SMN + SXN + 3) / 4) * 4;   // 16B-aligned
    constexpr int SWN = CH * K * K * 16;     // staged weights

    extern __shared__ float sm[];
    float* sMk = sm;                         // [IH][IW]
    float* sX  = sm + SMN;                   // [CH][IW][IHP]
    float* sW  = sm + SWOFF;                 // [CH][K][K][16co]
    float* sR  = sm + SWOFF + SWN;           // 128 floats reduce buf

    const int tid = threadIdx.x;
    const int n = blockIdx.z;
    const int x0 = blockIdx.x * TX - P;
    const int y0 = blockIdx.y * TY - P;

    // mask tile (zero pad OOB)
    const float* mkn = mk + (long long)n * mkNS;
    for (int i = tid; i < SMN; i += 128) {
        int ly = i / IW, lx = i - ly * IW;
        int gy = y0 + ly, gx = x0 + lx;
        float m = 0.f;
        if (gy >= 0 && gy < 1024 && gx >= 0 && gx < 1024) m = mkn[gy * IMW + gx];
        sMk[i] = m;
    }

    const int tx = tid & 31;   // x within output tile
    const int tq = tid >> 5;   // y quad (4 rows each)
    const float* inn = in + (long long)n * inNS;

    u64 acc2[32];              // [cp(8)][py(4)]  lo=co 2cp, hi=co 2cp+1
#pragma unroll
    for (int i = 0; i < 32; i++) acc2[i] = 0ull;

    for (int c0 = 0; c0 < CIN; c0 += CH) {
        __syncthreads();   // protect prior chunk's sX/sW (and mask on iter 0)

        // stage input chunk: masked (+ BN affine + relu) into col-major sX
        for (int ci = 0; ci < CH; ci++) {
            float2 ab = make_float2(1.f, 0.f);
            if (AFF) ab = aff[c0 + ci];
            const float* ip = inn + (long long)(c0 + ci) * HW;
            for (int i = tid; i < SMN; i += 128) {
                int ly = i / IW, lx = i - ly * IW;
                int gy = y0 + ly, gx = x0 + lx;
                float v = 0.f;
                if (gy >= 0 && gy < 1024 && gx >= 0 && gx < 1024) {
                    v = ip[gy * IMW + gx];
                    if (AFF) v = fmaxf(fmaf(v, ab.x, ab.y), 0.f);
                    v *= sMk[i];
                }
                sX[ci * (IW * IHP) + lx * IHP + ly] = v;
            }
        }
        // stage weight chunk: wG[co][ci][dy][dx] -> sW[ci'][dy][dx][co]
        for (int i = tid; i < SWN; i += 128) {
            int co = i & 15;
            int rest = i >> 4;                       // ci'*K*K + dy*K + dx
            sW[i] = wG[co * (CIN * K * K) + c0 * (K * K) + rest];
        }
        __syncthreads();

#pragma unroll 1
        for (int ci = 0; ci < CH; ci++) {
            const float* colbase = sX + ci * (IW * IHP) + tx * IHP + tq * 4;
            const float* wbase = sW + ci * (K * K * 16);
#pragma unroll 1
            for (int dx = 0; dx < K; dx++) {
                const float* colp = colbase + dx * IHP;
                u64 vv[K + 3];
#pragma unroll
                for (int j = 0; j < K + 3; j++) vv[j] = dup2(colp[j]);
#pragma unroll
                for (int dy = 0; dy < K; dy++) {
                    const ulonglong2* wq =
                        (const ulonglong2*)(wbase + (dy * K + dx) * 16);
                    ulonglong2 wa = wq[0];
                    ulonglong2 wb = wq[1];
                    ulonglong2 wc = wq[2];
                    ulonglong2 wd = wq[3];
#pragma unroll
                    for (int py = 0; py < 4; py++) {
                        u64 v = vv[dy + py];
                        fma2(acc2[0 * 4 + py], v, wa.x);
                        fma2(acc2[1 * 4 + py], v, wa.y);
                        fma2(acc2[2 * 4 + py], v, wb.x);
                        fma2(acc2[3 * 4 + py], v, wb.y);
                        fma2(acc2[4 * 4 + py], v, wc.x);
                        fma2(acc2[5 * 4 + py], v, wc.y);
                        fma2(acc2[6 * 4 + py], v, wd.x);
                        fma2(acc2[7 * 4 + py], v, wd.y);
                    }
                }
            }
        }
    }

    // mask-sum conv + mask maxpool from the smem mask tile
    float s[4] = {0.f, 0.f, 0.f, 0.f};
    float mm[4] = {0.f, 0.f, 0.f, 0.f};
    {
        const float* mb = sMk + (tq * 4) * IW + tx;
#pragma unroll 1
        for (int dy = 0; dy < K; dy++) {
#pragma unroll
            for (int dx = 0; dx < K; dx++) {
#pragma unroll
                for (int py = 0; py < 4; py++) {
                    float m = mb[(dy + py) * IW + dx];
                    s[py] += m;
                    mm[py] = fmaxf(mm[py], m);
                }
            }
        }
    }
    float inv[4];
#pragma unroll
    for (int py = 0; py < 4; py++) inv[py] = 1.0f / (s[py] + 1e-8f);

    const int gy = blockIdx.y * TY + tq * 4;
    const int gx = blockIdx.x * TX + tx;

    float* mo = outM + (long long)n * HW + gy * IMW + gx;
#pragma unroll
    for (int py = 0; py < 4; py++) mo[py * IMW] = mm[py];

    float* ho = outH + ((long long)n * 16) * HW + gy * IMW + gx;
    const int lane = tid & 31;
    const int warp = tid >> 5;
#pragma unroll
    for (int cp = 0; cp < 8; cp++) {
        float b0 = bias[2 * cp], b1 = bias[2 * cp + 1];
        float p1a = 0.f, p2a = 0.f, p1b = 0.f, p2b = 0.f;
#pragma unroll
        for (int py = 0; py < 4; py++) {
            float a0, a1;
            unpk(a0, a1, acc2[cp * 4 + py]);
            float y0v = fmaf(a0, inv[py], b0);
            float y1v = fmaf(a1, inv[py], b1);
            ho[(long long)(2 * cp) * HW + py * IMW] = y0v;
            ho[(long long)(2 * cp + 1) * HW + py * IMW] = y1v;
            p1a += y0v; p2a = fmaf(y0v, y0v, p2a);
            p1b += y1v; p2b = fmaf(y1v, y1v, p2b);
        }
#pragma unroll
        for (int o = 16; o; o >>= 1) {
            p1a += __shfl_xor_sync(0xffffffffu, p1a, o);
            p2a += __shfl_xor_sync(0xffffffffu, p2a, o);
            p1b += __shfl_xor_sync(0xffffffffu, p1b, o);
            p2b += __shfl_xor_sync(0xffffffffu, p2b, o);
        }
        if (lane == 0) {
            sR[((2 * cp) * 2 + 0) * 4 + warp] = p1a;
            sR[((2 * cp) * 2 + 1) * 4 + warp] = p2a;
            sR[((2 * cp + 1) * 2 + 0) * 4 + warp] = p1b;
            sR[((2 * cp + 1) * 2 + 1) * 4 + warp] = p2b;
        }
    }
    __syncthreads();
    if (tid < 32) {
        float v = sR[tid * 4 + 0] + sR[tid * 4 + 1] + sR[tid * 4 + 2] + sR[tid * 4 + 3];
        int co = tid >> 1, which = tid & 1;
        atomicAdd(&stats[which * 16 + co], (double)v);
    }
}

// ---------------------------------------------------------------------------
// Layer 6: 1x1 partial conv, 16 -> 1 channel.
// ---------------------------------------------------------------------------
__global__ void conv1x1_k(const float* __restrict__ h,
                          const float* __restrict__ mk,
                          const float* __restrict__ w6,
                          const float* __restrict__ b6,
                          const float2* __restrict__ aff,
                          float* __restrict__ y,
                          double* __restrict__ stats) {
    __shared__ float swv[16];
    __shared__ float2 sab[16];
    __shared__ float r1[8], r2[8];
    if (threadIdx.x < 16) {
        swv[threadIdx.x] = w6[threadIdx.x];
        sab[threadIdx.x] = aff[threadIdx.x];
    }
    __syncthreads();
    float bb = b6[0];
    float p1 = 0.f, p2 = 0.f;
    for (long long i = (long long)blockIdx.x * blockDim.x + threadIdx.x;
         i < 4LL * HW; i += (long long)gridDim.x * blockDim.x) {
        long long n = i >> 20;
        long long p = i & (HW - 1);
        float m = mk[i];
        float accv = 0.f;
#pragma unroll
        for (int c = 0; c < 16; c++) {
            float v = h[(n * 16 + c) * HW + p];
            float2 ab = sab[c];
            v = fmaxf(fmaf(v, ab.x, ab.y), 0.f);
            accv = fmaf(swv[c], v, accv);
        }
        float r = 1.0f / (m + 1e-8f);
        float yv = fmaf(accv * m, r, bb);
        y[i] = yv;
        p1 += yv;
        p2 = fmaf(yv, yv, p2);
    }
#pragma unroll
    for (int o = 16; o; o >>= 1) {
        p1 += __shfl_xor_sync(0xffffffffu, p1, o);
        p2 += __shfl_xor_sync(0xffffffffu, p2, o);
    }
    int warp = threadIdx.x >> 5, lane = threadIdx.x & 31;
    if (lane == 0) { r1[warp] = p1; r2[warp] = p2; }
    __syncthreads();
    if (threadIdx.x == 0) {
        float a = 0.f, b = 0.f;
        for (int w = 0; w < (int)(blockDim.x >> 5); w++) { a += r1[w]; b += r2[w]; }
        atomicAdd(&stats[0], (double)a);
        atomicAdd(&stats[16], (double)b);
    }
}

__global__ void final_k(const float* __restrict__ y,
                        const float2* __restrict__ ab,
                        float* __restrict__ o) {
    float2 t = ab[0];
    for (long long i = (long long)blockIdx.x * blockDim.x + threadIdx.x;
         i < 4LL * HW; i += (long long)gridDim.x * blockDim.x)
        o[i] = fmaf(y[i], t.x, t.y);
}

// ---------------------------------------------------------------------------
static constexpr int smem_bytes(int K, int CH) {
    int IW = 32 + K - 1, IH = 16 + K - 1;
    int IHP = IH | 1;
    int smn = IH * IW;
    int sxn = CH * IW * IHP;
    int swoff = ((smn + sxn + 3) / 4) * 4;
    return (swoff + CH * K * K * 16 + 128) * 4;
}

extern "C" void kernel_launch(void* const* d_in, const int* in_sizes, int n_in,
                              void* d_out, int out_size) {
    (void)in_sizes; (void)n_in; (void)out_size;
    const float* x = (const float*)d_in[0];
    const float *wp[6], *bp[6], *gp[6], *btp[6];
    for (int i = 0; i < 6; i++) {
        wp[i]  = (const float*)d_in[1 + 4 * i];
        bp[i]  = (const float*)d_in[2 + 4 * i];
        gp[i]  = (const float*)d_in[3 + 4 * i];
        btp[i] = (const float*)d_in[4 + 4 * i];
    }

    float *h0, *h1, *m0, *m1;
    double* st;
    float2* ab;
    cudaGetSymbolAddress((void**)&h0, g_h0);
    cudaGetSymbolAddress((void**)&h1, g_h1);
    cudaGetSymbolAddress((void**)&m0, g_m0);
    cudaGetSymbolAddress((void**)&m1, g_m1);
    cudaGetSymbolAddress((void**)&st, g_stats);
    cudaGetSymbolAddress((void**)&ab, g_affine);

    cudaFuncSetAttribute(conv_k<11, 1, 1, false>, cudaFuncAttributeMaxDynamicSharedMemorySize, smem_bytes(11, 1));
    cudaFuncSetAttribute(conv_k<7, 16, 4, true>,  cudaFuncAttributeMaxDynamicSharedMemorySize, smem_bytes(7, 4));
    cudaFuncSetAttribute(conv_k<5, 16, 4, true>,  cudaFuncAttributeMaxDynamicSharedMemorySize, smem_bytes(5, 4));
    cudaFuncSetAttribute(conv_k<3, 16, 4, true>,  cudaFuncAttributeMaxDynamicSharedMemorySize, smem_bytes(3, 4));

    dim3 grid(1024 / 32, 1024 / 16, 4);
    dim3 blk(128);

    zero_stats_k<<<1, 192>>>();

    conv_k<11, 1, 1, false><<<grid, blk, smem_bytes(11, 1)>>>(
        x, 2LL * HW, x + HW, 2LL * HW, wp[0], bp[0], nullptr, h0, m0, st + 0);
    affine_k<<<1, 16>>>(st + 0, gp[0], btp[0], ab + 0, 16);

    conv_k<7, 16, 4, true><<<grid, blk, smem_bytes(7, 4)>>>(
        h0, 16LL * HW, m0, (long long)HW, wp[1], bp[1], ab + 0, h1, m1, st + 32);
    affine_k<<<1, 16>>>(st + 32, gp[1], btp[1], ab + 16, 16);

    conv_k<5, 16, 4, true><<<grid, blk, smem_bytes(5, 4)>>>(
        h1, 16LL * HW, m1, (long long)HW, wp[2], bp[2], ab + 16, h0, m0, st + 64);
    affine_k<<<1, 16>>>(st + 64, gp[2], btp[2], ab + 32, 16);

    conv_k<3, 16, 4, true><<<grid, blk, smem_bytes(3, 4)>>>(
        h0, 16LL * HW, m0, (long long)HW, wp[3], bp[3], ab + 32, h1, m1, st + 96);
    affine_k<<<1, 16>>>(st + 96, gp[3], btp[3], ab + 48, 16);

    conv_k<3, 16, 4, true><<<grid, blk, smem_bytes(3, 4)>>>(
        h1, 16LL * HW, m1, (long long)HW, wp[4], bp[4], ab + 48, h0, m0, st + 128);
    affine_k<<<1, 16>>>(st + 128, gp[4], btp[4], ab + 64, 16);

    conv1x1_k<<<1184, 256>>>(h0, m0, wp[5], bp[5], ab + 64, h1, st + 160);
    affine_k<<<1, 16>>>(st + 160, gp[5], btp[5], ab + 80, 1);

    final_k<<<4096, 256>>>(h1, ab + 80, (float*)d_out);
}

// round 3
// speedup vs baseline: 1.8324x; 1.2782x over previous
#include <cuda_runtime.h>
#include <math.h>

// ---------------------------------------------------------------------------
// SparseConvNet: 6 partial-conv layers. N=4, H=W=1024.
// Layers: (1,16,11)(16,16,7)(16,16,5)(16,16,3)(16,16,3)(16,1,1)
// Round 3: hoisted staging index math, register-cached affines, CH=8 chunks
//          for k<=5 layers. Inner loop unchanged (FFMA2 over channel pairs).
// ---------------------------------------------------------------------------

#define HW   (1024 * 1024)
#define IMW  1024
#define NPIX (4LL * HW)

__device__ float  g_h0[4 * 16 * HW];
__device__ float  g_h1[4 * 16 * HW];
__device__ float  g_m0[4 * HW];
__device__ float  g_m1[4 * HW];
__device__ double g_stats[6 * 32];
__device__ float2 g_affine[6 * 16];

typedef unsigned long long u64;

__device__ __forceinline__ u64 dup2(float v) {
    u64 r;
    asm("mov.b64 %0, {%1, %1};" : "=l"(r) : "f"(v));
    return r;
}
__device__ __forceinline__ void fma2(u64& d, u64 a, u64 b) {
    asm("fma.rn.f32x2 %0, %1, %2, %0;" : "+l"(d) : "l"(a), "l"(b));
}
__device__ __forceinline__ void unpk(float& lo, float& hi, u64 v) {
    asm("mov.b64 {%0, %1}, %2;" : "=f"(lo), "=f"(hi) : "l"(v));
}

__global__ void zero_stats_k() {
    if (threadIdx.x < 6 * 32) g_stats[threadIdx.x] = 0.0;
}

__global__ void affine_k(const double* __restrict__ st,
                         const float* __restrict__ gam,
                         const float* __restrict__ bet,
                         float2* __restrict__ ab, int nch) {
    int c = threadIdx.x;
    if (c >= nch) return;
    double mean = st[c] / (double)NPIX;
    double var  = st[16 + c] / (double)NPIX - mean * mean;
    float inv = rsqrtf((float)var + 1e-5f);
    float a = gam[c] * inv;
    ab[c] = make_float2(a, bet[c] - (float)mean * a);
}

// ---------------------------------------------------------------------------
// Fused partial-conv layer. Output tile 32x16, 128 threads, 4 px/thread,
// 16 output channels as 8 packed f32x2 channel-pairs.
// ---------------------------------------------------------------------------
template <int K, int CIN, int CH, bool AFF>
__global__ void __launch_bounds__(128, 4) conv_k(
    const float* __restrict__ in, long long inNS,
    const float* __restrict__ mk, long long mkNS,
    const float* __restrict__ wG, const float* __restrict__ bias,
    const float2* __restrict__ aff,
    float* __restrict__ outH, float* __restrict__ outM,
    double* __restrict__ stats) {
    constexpr int TX = 32, TY = 16, P = K / 2;
    constexpr int IW = TX + K - 1;           // input tile width
    constexpr int IH = TY + K - 1;           // input tile height
    constexpr int IHP = IH | 1;              // odd row pitch (col-major)
    constexpr int SMN = IH * IW;             // mask tile (row-major)
    constexpr int SXN = CH * IW * IHP;       // staged input (col-major)
    constexpr int SWOFF = ((SMN + SXN + 3) / 4) * 4;   // 16B-aligned
    constexpr int SWN = CH * K * K * 16;     // staged weights

    extern __shared__ float sm[];
    float* sMk = sm;                         // [IH][IW]
    float* sX  = sm + SMN;                   // [CH][IW][IHP]
    float* sW  = sm + SWOFF;                 // [CH][K][K][16co]
    float* sR  = sm + SWOFF + SWN;           // 128 floats reduce buf

    const int tid = threadIdx.x;
    const int n = blockIdx.z;
    const int x0 = blockIdx.x * TX - P;
    const int y0 = blockIdx.y * TY - P;

    // mask tile (zero pad OOB)
    const float* mkn = mk + (long long)n * mkNS;
    for (int i = tid; i < SMN; i += 128) {
        int ly = i / IW, lx = i - ly * IW;
        int gy = y0 + ly, gx = x0 + lx;
        float m = 0.f;
        if ((unsigned)gy < 1024u && (unsigned)gx < 1024u) m = mkn[gy * IMW + gx];
        sMk[i] = m;
    }

    const int tx = tid & 31;   // x within output tile
    const int tq = tid >> 5;   // y quad (4 rows each)
    const float* inn = in + (long long)n * inNS;

    u64 acc2[32];              // [cp(8)][py(4)]  lo=co 2cp, hi=co 2cp+1
#pragma unroll
    for (int i = 0; i < 32; i++) acc2[i] = 0ull;

    for (int c0 = 0; c0 < CIN; c0 += CH) {
        __syncthreads();   // protect prior chunk's sX/sW (and mask on iter 0)

        // cache BN affine coefficients for this chunk in registers
        float2 abr[CH];
#pragma unroll
        for (int ci = 0; ci < CH; ci++)
            abr[ci] = AFF ? aff[c0 + ci] : make_float2(1.f, 0.f);

        // stage input chunk: masked (+ BN affine + relu) into col-major sX.
        // index math computed once per pixel, all CH channels loaded together.
        const float* ipc = inn + (long long)c0 * HW;
        for (int i = tid; i < SMN; i += 128) {
            int ly = i / IW, lx = i - ly * IW;
            int gy = y0 + ly, gx = x0 + lx;
            bool ok = (unsigned)gy < 1024u && (unsigned)gx < 1024u;
            float m = sMk[i];
            int so = lx * IHP + ly;
            const float* p = ipc + (long long)gy * IMW + gx;
            float v[CH];
#pragma unroll
            for (int ci = 0; ci < CH; ci++) {
                v[ci] = 0.f;
                if (ok) v[ci] = p[(long long)ci * HW];
            }
#pragma unroll
            for (int ci = 0; ci < CH; ci++) {
                float t = v[ci];
                if (AFF) t = fmaxf(fmaf(t, abr[ci].x, abr[ci].y), 0.f);
                sX[ci * (IW * IHP) + so] = t * m;
            }
        }
        // stage weight chunk: wG[co][ci][dy][dx] -> sW[ci'][dy][dx][co]
        for (int i = tid; i < SWN; i += 128) {
            int co = i & 15;
            int rest = i >> 4;                       // ci'*K*K + dy*K + dx
            sW[i] = wG[co * (CIN * K * K) + c0 * (K * K) + rest];
        }
        __syncthreads();

#pragma unroll 1
        for (int ci = 0; ci < CH; ci++) {
            const float* colbase = sX + ci * (IW * IHP) + tx * IHP + tq * 4;
            const float* wbase = sW + ci * (K * K * 16);
#pragma unroll 1
            for (int dx = 0; dx < K; dx++) {
                const float* colp = colbase + dx * IHP;
                u64 vv[K + 3];
#pragma unroll
                for (int j = 0; j < K + 3; j++) vv[j] = dup2(colp[j]);
#pragma unroll
                for (int dy = 0; dy < K; dy++) {
                    const ulonglong2* wq =
                        (const ulonglong2*)(wbase + (dy * K + dx) * 16);
                    ulonglong2 wa = wq[0];
                    ulonglong2 wb = wq[1];
                    ulonglong2 wc = wq[2];
                    ulonglong2 wd = wq[3];
#pragma unroll
                    for (int py = 0; py < 4; py++) {
                        u64 v = vv[dy + py];
                        fma2(acc2[0 * 4 + py], v, wa.x);
                        fma2(acc2[1 * 4 + py], v, wa.y);
                        fma2(acc2[2 * 4 + py], v, wb.x);
                        fma2(acc2[3 * 4 + py], v, wb.y);
                        fma2(acc2[4 * 4 + py], v, wc.x);
                        fma2(acc2[5 * 4 + py], v, wc.y);
                        fma2(acc2[6 * 4 + py], v, wd.x);
                        fma2(acc2[7 * 4 + py], v, wd.y);
                    }
                }
            }
        }
    }

    // mask-sum conv + mask maxpool from the smem mask tile
    float s[4] = {0.f, 0.f, 0.f, 0.f};
    float mm[4] = {0.f, 0.f, 0.f, 0.f};
    {
        const float* mb = sMk + (tq * 4) * IW + tx;
#pragma unroll 1
        for (int dy = 0; dy < K; dy++) {
#pragma unroll
            for (int dx = 0; dx < K; dx++) {
#pragma unroll
                for (int py = 0; py < 4; py++) {
                    float m = mb[(dy + py) * IW + dx];
                    s[py] += m;
                    mm[py] = fmaxf(mm[py], m);
                }
            }
        }
    }
    float inv[4];
#pragma unroll
    for (int py = 0; py < 4; py++) inv[py] = 1.0f / (s[py] + 1e-8f);

    const int gy = blockIdx.y * TY + tq * 4;
    const int gx = blockIdx.x * TX + tx;

    float* mo = outM + (long long)n * HW + gy * IMW + gx;
#pragma unroll
    for (int py = 0; py < 4; py++) mo[py * IMW] = mm[py];

    float* ho = outH + ((long long)n * 16) * HW + gy * IMW + gx;
    const int lane = tid & 31;
    const int warp = tid >> 5;
#pragma unroll
    for (int cp = 0; cp < 8; cp++) {
        float b0 = bias[2 * cp], b1 = bias[2 * cp + 1];
        float p1a = 0.f, p2a = 0.f, p1b = 0.f, p2b = 0.f;
#pragma unroll
        for (int py = 0; py < 4; py++) {
            float a0, a1;
            unpk(a0, a1, acc2[cp * 4 + py]);
            float y0v = fmaf(a0, inv[py], b0);
            float y1v = fmaf(a1, inv[py], b1);
            ho[(long long)(2 * cp) * HW + py * IMW] = y0v;
            ho[(long long)(2 * cp + 1) * HW + py * IMW] = y1v;
            p1a += y0v; p2a = fmaf(y0v, y0v, p2a);
            p1b += y1v; p2b = fmaf(y1v, y1v, p2b);
        }
#pragma unroll
        for (int o = 16; o; o >>= 1) {
            p1a += __shfl_xor_sync(0xffffffffu, p1a, o);
            p2a += __shfl_xor_sync(0xffffffffu, p2a, o);
            p1b += __shfl_xor_sync(0xffffffffu, p1b, o);
            p2b += __shfl_xor_sync(0xffffffffu, p2b, o);
        }
        if (lane == 0) {
            sR[((2 * cp) * 2 + 0) * 4 + warp] = p1a;
            sR[((2 * cp) * 2 + 1) * 4 + warp] = p2a;
            sR[((2 * cp + 1) * 2 + 0) * 4 + warp] = p1b;
            sR[((2 * cp + 1) * 2 + 1) * 4 + warp] = p2b;
        }
    }
    __syncthreads();
    if (tid < 32) {
        float v = sR[tid * 4 + 0] + sR[tid * 4 + 1] + sR[tid * 4 + 2] + sR[tid * 4 + 3];
        int co = tid >> 1, which = tid & 1;
        atomicAdd(&stats[which * 16 + co], (double)v);
    }
}

// ---------------------------------------------------------------------------
// Layer 6: 1x1 partial conv, 16 -> 1 channel.
// ---------------------------------------------------------------------------
__global__ void conv1x1_k(const float* __restrict__ h,
                          const float* __restrict__ mk,
                          const float* __restrict__ w6,
                          const float* __restrict__ b6,
                          const float2* __restrict__ aff,
                          float* __restrict__ y,
                          double* __restrict__ stats) {
    __shared__ float swv[16];
    __shared__ float2 sab[16];
    __shared__ float r1[8], r2[8];
    if (threadIdx.x < 16) {
        swv[threadIdx.x] = w6[threadIdx.x];
        sab[threadIdx.x] = aff[threadIdx.x];
    }
    __syncthreads();
    float bb = b6[0];
    float p1 = 0.f, p2 = 0.f;
    for (long long i = (long long)blockIdx.x * blockDim.x + threadIdx.x;
         i < 4LL * HW; i += (long long)gridDim.x * blockDim.x) {
        long long n = i >> 20;
        long long p = i & (HW - 1);
        float m = mk[i];
        float accv = 0.f;
#pragma unroll
        for (int c = 0; c < 16; c++) {
            float v = h[(n * 16 + c) * HW + p];
            float2 ab = sab[c];
            v = fmaxf(fmaf(v, ab.x, ab.y), 0.f);
            accv = fmaf(swv[c], v, accv);
        }
        float r = 1.0f / (m + 1e-8f);
        float yv = fmaf(accv * m, r, bb);
        y[i] = yv;
        p1 += yv;
        p2 = fmaf(yv, yv, p2);
    }
#pragma unroll
    for (int o = 16; o; o >>= 1) {
        p1 += __shfl_xor_sync(0xffffffffu, p1, o);
        p2 += __shfl_xor_sync(0xffffffffu, p2, o);
    }
    int warp = threadIdx.x >> 5, lane = threadIdx.x & 31;
    if (lane == 0) { r1[warp] = p1; r2[warp] = p2; }
    __syncthreads();
    if (threadIdx.x == 0) {
        float a = 0.f, b = 0.f;
        for (int w = 0; w < (int)(blockDim.x >> 5); w++) { a += r1[w]; b += r2[w]; }
        atomicAdd(&stats[0], (double)a);
        atomicAdd(&stats[16], (double)b);
    }
}

__global__ void final_k(const float* __restrict__ y,
                        const float2* __restrict__ ab,
                        float* __restrict__ o) {
    float2 t = ab[0];
    for (long long i = (long long)blockIdx.x * blockDim.x + threadIdx.x;
         i < 4LL * HW; i += (long long)gridDim.x * blockDim.x)
        o[i] = fmaf(y[i], t.x, t.y);
}

// ---------------------------------------------------------------------------
static constexpr int smem_bytes(int K, int CH) {
    int IW = 32 + K - 1, IH = 16 + K - 1;
    int IHP = IH | 1;
    int smn = IH * IW;
    int sxn = CH * IW * IHP;
    int swoff = ((smn + sxn + 3) / 4) * 4;
    return (swoff + CH * K * K * 16 + 128) * 4;
}

extern "C" void kernel_launch(void* const* d_in, const int* in_sizes, int n_in,
                              void* d_out, int out_size) {
    (void)in_sizes; (void)n_in; (void)out_size;
    const float* x = (const float*)d_in[0];
    const float *wp[6], *bp[6], *gp[6], *btp[6];
    for (int i = 0; i < 6; i++) {
        wp[i]  = (const float*)d_in[1 + 4 * i];
        bp[i]  = (const float*)d_in[2 + 4 * i];
        gp[i]  = (const float*)d_in[3 + 4 * i];
        btp[i] = (const float*)d_in[4 + 4 * i];
    }

    float *h0, *h1, *m0, *m1;
    double* st;
    float2* ab;
    cudaGetSymbolAddress((void**)&h0, g_h0);
    cudaGetSymbolAddress((void**)&h1, g_h1);
    cudaGetSymbolAddress((void**)&m0, g_m0);
    cudaGetSymbolAddress((void**)&m1, g_m1);
    cudaGetSymbolAddress((void**)&st, g_stats);
    cudaGetSymbolAddress((void**)&ab, g_affine);

    cudaFuncSetAttribute(conv_k<11, 1, 1, false>, cudaFuncAttributeMaxDynamicSharedMemorySize, smem_bytes(11, 1));
    cudaFuncSetAttribute(conv_k<7, 16, 4, true>,  cudaFuncAttributeMaxDynamicSharedMemorySize, smem_bytes(7, 4));
    cudaFuncSetAttribute(conv_k<5, 16, 8, true>,  cudaFuncAttributeMaxDynamicSharedMemorySize, smem_bytes(5, 8));
    cudaFuncSetAttribute(conv_k<3, 16, 8, true>,  cudaFuncAttributeMaxDynamicSharedMemorySize, smem_bytes(3, 8));

    dim3 grid(1024 / 32, 1024 / 16, 4);
    dim3 blk(128);

    zero_stats_k<<<1, 192>>>();

    conv_k<11, 1, 1, false><<<grid, blk, smem_bytes(11, 1)>>>(
        x, 2LL * HW, x + HW, 2LL * HW, wp[0], bp[0], nullptr, h0, m0, st + 0);
    affine_k<<<1, 16>>>(st + 0, gp[0], btp[0], ab + 0, 16);

    conv_k<7, 16, 4, true><<<grid, blk, smem_bytes(7, 4)>>>(
        h0, 16LL * HW, m0, (long long)HW, wp[1], bp[1], ab + 0, h1, m1, st + 32);
    affine_k<<<1, 16>>>(st + 32, gp[1], btp[1], ab + 16, 16);

    conv_k<5, 16, 8, true><<<grid, blk, smem_bytes(5, 8)>>>(
        h1, 16LL * HW, m1, (long long)HW, wp[2], bp[2], ab + 16, h0, m0, st + 64);
    affine_k<<<1, 16>>>(st + 64, gp[2], btp[2], ab + 32, 16);

    conv_k<3, 16, 8, true><<<grid, blk, smem_bytes(3, 8)>>>(
        h0, 16LL * HW, m0, (long long)HW, wp[3], bp[3], ab + 32, h1, m1, st + 96);
    affine_k<<<1, 16>>>(st + 96, gp[3], btp[3], ab + 48, 16);

    conv_k<3, 16, 8, true><<<grid, blk, smem_bytes(3, 8)>>>(
        h1, 16LL * HW, m1, (long long)HW, wp[4], bp[4], ab + 48, h0, m0, st + 128);
    affine_k<<<1, 16>>>(st + 128, gp[4], btp[4], ab + 64, 16);

    conv1x1_k<<<1184, 256>>>(h0, m0, wp[5], bp[5], ab + 64, h1, st + 160);
    affine_k<<<1, 16>>>(st + 160, gp[5], btp[5], ab + 80, 1);

    final_k<<<4096, 256>>>(h1, ab + 80, (float*)d_out);
}